// round 13
// baseline (speedup 1.0000x reference)
#include <cuda_runtime.h>
#include <cuda_fp16.h>
#include <cstdint>

#define N_NODES 100000
#define E_EDGES 1600000
#define D 64

// Scratch (device globals: allocation-free per harness rules)
__device__ __half g_ahi[(size_t)N_NODES * D];   // hi fp16 plane of MLP input
__device__ __half g_alo[(size_t)N_NODES * D];   // lo fp16 plane of MLP input
__device__ float  g_buf[(size_t)N_NODES * D];   // fp32 inter-block features
__device__ int    g_deg[N_NODES];
__device__ int    g_cur[N_NODES];
__device__ int    g_off[N_NODES];
__device__ int    g_srcs[E_EDGES];
__device__ int    g_part[128];
__device__ int    g_ei_is64;

// ===========================================================================
// zero + edge-index dtype probe (merged; probe in block 0)
// ===========================================================================
__global__ void zero_probe_kernel(const int* __restrict__ ei_i32) {
    __shared__ int nz;
    int t = threadIdx.x;
    int i = blockIdx.x * blockDim.x + t;
    if (i < N_NODES) { g_deg[i] = 0; g_cur[i] = 0; }
    if (blockIdx.x == 0) {
        if (t == 0) nz = 0;
        __syncthreads();
        if (t < 128 && ei_i32[2 * t + 1] != 0) atomicOr(&nz, 1);
        __syncthreads();
        if (t == 0) g_ei_is64 = (nz == 0) ? 1 : 0;
    }
}

__device__ __forceinline__ int load_idx(const void* ei_raw, int pos) {
    if (g_ei_is64) return (int)__ldg(&((const long long*)ei_raw)[pos]);
    return __ldg(&((const int*)ei_raw)[pos]);
}

__global__ void hist_kernel(const void* __restrict__ ei_raw) {
    int e = blockIdx.x * blockDim.x + threadIdx.x;
    if (e >= E_EDGES) return;
    atomicAdd(&g_deg[load_idx(ei_raw, E_EDGES + e)], 1);
}

__global__ void __launch_bounds__(1024) scan1_kernel() {
    __shared__ int wsum[32];
    int i = blockIdx.x * 1024 + threadIdx.x;
    int v = (i < N_NODES) ? g_deg[i] : 0;
    int lane = threadIdx.x & 31, wid = threadIdx.x >> 5;
    int incl = v;
    #pragma unroll
    for (int d = 1; d < 32; d <<= 1) {
        int n = __shfl_up_sync(~0u, incl, d);
        if (lane >= d) incl += n;
    }
    if (lane == 31) wsum[wid] = incl;
    __syncthreads();
    if (wid == 0) {
        int s = wsum[lane];
        #pragma unroll
        for (int d = 1; d < 32; d <<= 1) {
            int n = __shfl_up_sync(~0u, s, d);
            if (lane >= d) s += n;
        }
        wsum[lane] = s;
    }
    __syncthreads();
    int woff = (wid > 0) ? wsum[wid - 1] : 0;
    if (i < N_NODES) g_off[i] = woff + incl - v;
    if (threadIdx.x == 1023) g_part[blockIdx.x] = woff + incl;
}

__global__ void scan2_kernel(int nparts) {
    __shared__ int ws[4];
    int t = threadIdx.x;
    int v = (t < nparts) ? g_part[t] : 0;
    int lane = t & 31, w = t >> 5;
    int incl = v;
    #pragma unroll
    for (int d = 1; d < 32; d <<= 1) {
        int n = __shfl_up_sync(~0u, incl, d);
        if (lane >= d) incl += n;
    }
    if (lane == 31) ws[w] = incl;
    __syncthreads();
    int add = 0;
    #pragma unroll
    for (int k = 0; k < 4; k++) if (k < w) add += ws[k];
    if (t < nparts) g_part[t] = add + incl - v;
}

__global__ void __launch_bounds__(1024) scan3_kernel() {
    int i = blockIdx.x * 1024 + threadIdx.x;
    if (i < N_NODES) g_off[i] += g_part[blockIdx.x];
}

__global__ void fill_kernel(const void* __restrict__ ei_raw) {
    int e = blockIdx.x * blockDim.x + threadIdx.x;
    if (e >= E_EDGES) return;
    int src = load_idx(ei_raw, e);
    int dst = load_idx(ei_raw, E_EDGES + e);
    g_srcs[g_off[dst] + atomicAdd(&g_cur[dst], 1)] = src;
}

// ===========================================================================
// split helpers (exact fp16 decomposition of fp32)
// ===========================================================================
__device__ __forceinline__ void split1(float x, __half& h, __half& l) {
    h = __float2half_rn(x);
    l = __float2half_rn(x - __half2float(h));
}
__device__ __forceinline__ uint32_t packh2(__half a, __half b) {
    __half2 h = __halves2half2(a, b);
    return *(uint32_t*)&h;
}

// ===========================================================================
// aggregate: v = x[node] + sum_j x[srcs[j]]  (fp32 math) -> hi/lo fp16 planes.
// Memory-bound at the LTS wall; the split conversions ride for free.
// ===========================================================================
__global__ void __launch_bounds__(256) aggregate_kernel(
    const float* __restrict__ x, __half* __restrict__ ahi, __half* __restrict__ alo)
{
    int node = blockIdx.x * 16 + (threadIdx.x >> 4);
    int c = threadIdx.x & 15;
    if (node >= N_NODES) return;

    int beg = __ldg(&g_off[node]);
    int cnt = __ldg(&g_deg[node]);
    float4 v = __ldg((const float4*)(x + (size_t)node * D) + c);

    int j = 0;
    for (; j + 2 <= cnt; j += 2) {
        int s0 = __ldg(&g_srcs[beg + j]);
        int s1 = __ldg(&g_srcs[beg + j + 1]);
        float4 u0 = __ldg((const float4*)(x + (size_t)s0 * D) + c);
        float4 u1 = __ldg((const float4*)(x + (size_t)s1 * D) + c);
        v.x += u0.x + u1.x; v.y += u0.y + u1.y;
        v.z += u0.z + u1.z; v.w += u0.w + u1.w;
    }
    if (j < cnt) {
        int s0 = __ldg(&g_srcs[beg + j]);
        float4 u0 = __ldg((const float4*)(x + (size_t)s0 * D) + c);
        v.x += u0.x; v.y += u0.y; v.z += u0.z; v.w += u0.w;
    }

    __half h0, l0, h1, l1, h2, l2, h3, l3;
    split1(v.x, h0, l0); split1(v.y, h1, l1);
    split1(v.z, h2, l2); split1(v.w, h3, l3);
    size_t off = (size_t)node * D + c * 4;
    *(uint2*)(ahi + off) = make_uint2(packh2(h0, h1), packh2(h2, h3));
    *(uint2*)(alo + off) = make_uint2(packh2(l0, l1), packh2(l2, l3));
}

// ===========================================================================
// Tensor-core MLP via mma.sync.m16n8k16 FP16, 2-product split (R12 numerics).
// R13: A arrives as pre-split hi/lo fp16 planes -> staging is a PURE COPY
// (uint4 ld + STS.128), zero conversion ALU in the MLP.
// mode bit0: two-layer GIN block (relu both); bit1: write hi/lo planes out.
// CTA = 128 threads / 128 rows; warp w: rows 32w..32w+31, all 64 cols.
// ===========================================================================
#define SR 72

#define SM_BIAS1 0
#define SM_BIAS2 256
#define SM_AHI   512
#define SM_ALO   (SM_AHI + 128 * SR * 2)
#define SM_B1    (SM_ALO + 128 * SR * 2)
#define SM_B2    (SM_B1  + 64 * SR * 2)
#define SM_TOT   (SM_B2  + 64 * SR * 2)   // 55808 bytes -> 4 CTAs/SM

// NON-volatile: pure computation, lets the compiler schedule.
__device__ __forceinline__ void mma16816(float c[4], uint32_t a0, uint32_t a1,
                                         uint32_t a2, uint32_t a3,
                                         uint32_t b0, uint32_t b1) {
    asm("mma.sync.aligned.m16n8k16.row.col.f32.f16.f16.f32 "
        "{%0,%1,%2,%3}, {%4,%5,%6,%7}, {%8,%9}, {%0,%1,%2,%3};"
        : "+f"(c[0]), "+f"(c[1]), "+f"(c[2]), "+f"(c[3])
        : "r"(a0), "r"(a1), "r"(a2), "r"(a3), "r"(b0), "r"(b1));
}

// 2-product sweep: c += Ahi@B + Alo@B  (product-type outermost)
__device__ __forceinline__ void gemm_smemA(const __half* __restrict__ Ahi,
                                           const __half* __restrict__ Alo,
                                           const __half* __restrict__ B,
                                           float c[2][8][4], int m0, int g, int tig)
{
    #pragma unroll
    for (int ks = 0; ks < 4; ks++) {
        const int k0 = ks * 16;
        uint32_t ah[2][4], al[2][4];
        #pragma unroll
        for (int mt = 0; mt < 2; mt++) {
            const __half* p0 = Ahi + (m0 + mt * 16 + g) * SR + k0 + tig * 2;
            const __half* q0 = Alo + (m0 + mt * 16 + g) * SR + k0 + tig * 2;
            ah[mt][0] = *(const uint32_t*)p0;
            ah[mt][1] = *(const uint32_t*)(p0 + 8 * SR);
            ah[mt][2] = *(const uint32_t*)(p0 + 8);
            ah[mt][3] = *(const uint32_t*)(p0 + 8 * SR + 8);
            al[mt][0] = *(const uint32_t*)q0;
            al[mt][1] = *(const uint32_t*)(q0 + 8 * SR);
            al[mt][2] = *(const uint32_t*)(q0 + 8);
            al[mt][3] = *(const uint32_t*)(q0 + 8 * SR + 8);
        }
        #pragma unroll
        for (int nt = 0; nt < 8; nt++) {
            const __half* pb = B + (nt * 8 + g) * SR + k0 + tig * 2;
            uint32_t b0 = *(const uint32_t*)pb, b1 = *(const uint32_t*)(pb + 8);
            mma16816(c[0][nt], ah[0][0], ah[0][1], ah[0][2], ah[0][3], b0, b1);
            mma16816(c[1][nt], ah[1][0], ah[1][1], ah[1][2], ah[1][3], b0, b1);
        }
        #pragma unroll
        for (int nt = 0; nt < 8; nt++) {
            const __half* pb = B + (nt * 8 + g) * SR + k0 + tig * 2;
            uint32_t b0 = *(const uint32_t*)pb, b1 = *(const uint32_t*)(pb + 8);
            mma16816(c[0][nt], al[0][0], al[0][1], al[0][2], al[0][3], b0, b1);
            mma16816(c[1][nt], al[1][0], al[1][1], al[1][2], al[1][3], b0, b1);
        }
    }
}

// stage W^T (thread t<64 = row k of W): Wt[n][k] single fp16 plane
__device__ __forceinline__ void stage_w(const float* __restrict__ w,
                                        __half* b, int k)
{
    #pragma unroll 4
    for (int c4 = 0; c4 < 16; c4++) {
        float4 v = __ldg((const float4*)(w + k * 64) + c4);
        float fv[4] = {v.x, v.y, v.z, v.w};
        #pragma unroll
        for (int j = 0; j < 4; j++)
            b[(c4 * 4 + j) * SR + k] = __float2half_rn(fv[j]);
    }
}

__global__ void __launch_bounds__(128) mlp_tc_kernel(
    const __half* __restrict__ in_hi, const __half* __restrict__ in_lo,
    float* __restrict__ out_f32,
    __half* __restrict__ out_hi, __half* __restrict__ out_lo,
    const float* __restrict__ w1, const float* __restrict__ b1,
    const float* __restrict__ w2, const float* __restrict__ b2,
    int mode)   // bit0: two-layer + relu; bit1: write planes instead of fp32
{
    extern __shared__ char smem[];
    float* sB1f = (float*)(smem + SM_BIAS1);
    float* sB2f = (float*)(smem + SM_BIAS2);
    __half* sAhi = (__half*)(smem + SM_AHI);
    __half* sAlo = (__half*)(smem + SM_ALO);
    __half* sB1  = (__half*)(smem + SM_B1);
    __half* sB2  = (__half*)(smem + SM_B2);

    const int t = threadIdx.x;
    const int warp = t >> 5, lane = t & 31;
    const int g = lane >> 2, tig = lane & 3;
    const int m0 = warp * 32;
    const int row0 = blockIdx.x * 128;
    const int two_layer = mode & 1;

    // ---- stage A: pure copy of pre-split planes (no conversion ALU) ----
    // 128 rows x 64 halves per plane = 1024 uint4; 8 iters x 128 threads.
    #pragma unroll
    for (int i = 0; i < 8; i++) {
        int idx = t + i * 128;
        int r = idx >> 3, c8 = idx & 7;       // c8: which uint4 (8 halves)
        int gr = row0 + r;
        uint4 vh = make_uint4(0, 0, 0, 0), vl = make_uint4(0, 0, 0, 0);
        if (gr < N_NODES) {
            vh = __ldg((const uint4*)(in_hi + (size_t)gr * D) + c8);
            vl = __ldg((const uint4*)(in_lo + (size_t)gr * D) + c8);
        }
        *(uint4*)(sAhi + r * SR + c8 * 8) = vh;
        *(uint4*)(sAlo + r * SR + c8 * 8) = vl;
    }
    // ---- stage W1^T, W2^T (t<64), biases ----
    if (t < 64) {
        stage_w(w1, sB1, t);
        if (two_layer) stage_w(w2, sB2, t);
    } else if (t < 80) {
        ((float4*)sB1f)[t - 64] = __ldg((const float4*)b1 + (t - 64));
    } else if (t < 96 && two_layer) {
        ((float4*)sB2f)[t - 80] = __ldg((const float4*)b2 + (t - 80));
    }
    __syncthreads();   // the ONLY barrier

    float c[2][8][4];
    #pragma unroll
    for (int mt = 0; mt < 2; mt++)
        #pragma unroll
        for (int nt = 0; nt < 8; nt++)
            #pragma unroll
            for (int j = 0; j < 4; j++) c[mt][nt][j] = 0.f;

    gemm_smemA(sAhi, sAlo, sB1, c, m0, g, tig);

    if (two_layer) {
        // ---- h1 = relu(c + b1): fp16 split/pack IN REGISTERS ----
        uint32_t phi[2][8][2], plo[2][8][2];
        #pragma unroll
        for (int mt = 0; mt < 2; mt++) {
            #pragma unroll
            for (int nt = 0; nt < 8; nt++) {
                int cb = nt * 8 + tig * 2;
                float o0 = fmaxf(c[mt][nt][0] + sB1f[cb],     0.f);
                float o1 = fmaxf(c[mt][nt][1] + sB1f[cb + 1], 0.f);
                float o2 = fmaxf(c[mt][nt][2] + sB1f[cb],     0.f);
                float o3 = fmaxf(c[mt][nt][3] + sB1f[cb + 1], 0.f);
                __half h0, l0, h1, l1, h2, l2, h3, l3;
                split1(o0, h0, l0); split1(o1, h1, l1);
                split1(o2, h2, l2); split1(o3, h3, l3);
                phi[mt][nt][0] = packh2(h0, h1);
                phi[mt][nt][1] = packh2(h2, h3);
                plo[mt][nt][0] = packh2(l0, l1);
                plo[mt][nt][1] = packh2(l2, l3);
            }
        }
        #pragma unroll
        for (int mt = 0; mt < 2; mt++)
            #pragma unroll
            for (int nt = 0; nt < 8; nt++)
                #pragma unroll
                for (int j = 0; j < 4; j++) c[mt][nt][j] = 0.f;

        // ---- layer-2 GEMM: A from registers, 2 products ----
        #pragma unroll
        for (int ks = 0; ks < 4; ks++) {
            const int k0 = ks * 16;
            #pragma unroll
            for (int nt = 0; nt < 8; nt++) {
                const __half* pb = sB2 + (nt * 8 + g) * SR + k0 + tig * 2;
                uint32_t b0 = *(const uint32_t*)pb, b1 = *(const uint32_t*)(pb + 8);
                mma16816(c[0][nt], phi[0][2*ks][0], phi[0][2*ks][1],
                         phi[0][2*ks+1][0], phi[0][2*ks+1][1], b0, b1);
                mma16816(c[1][nt], phi[1][2*ks][0], phi[1][2*ks][1],
                         phi[1][2*ks+1][0], phi[1][2*ks+1][1], b0, b1);
            }
            #pragma unroll
            for (int nt = 0; nt < 8; nt++) {
                const __half* pb = sB2 + (nt * 8 + g) * SR + k0 + tig * 2;
                uint32_t b0 = *(const uint32_t*)pb, b1 = *(const uint32_t*)(pb + 8);
                mma16816(c[0][nt], plo[0][2*ks][0], plo[0][2*ks][1],
                         plo[0][2*ks+1][0], plo[0][2*ks+1][1], b0, b1);
                mma16816(c[1][nt], plo[1][2*ks][0], plo[1][2*ks][1],
                         plo[1][2*ks+1][0], plo[1][2*ks+1][1], b0, b1);
            }
        }
    }

    // ---- epilogue: bias (+ relu for GIN block), store fp32 or planes ----
    const float* bias = two_layer ? sB2f : sB1f;
    #pragma unroll
    for (int mt = 0; mt < 2; mt++) {
        int r0 = row0 + m0 + mt * 16 + g;
        int r1 = r0 + 8;
        #pragma unroll
        for (int nt = 0; nt < 8; nt++) {
            int cb = nt * 8 + tig * 2;
            float o0 = c[mt][nt][0] + bias[cb];
            float o1 = c[mt][nt][1] + bias[cb + 1];
            float o2 = c[mt][nt][2] + bias[cb];
            float o3 = c[mt][nt][3] + bias[cb + 1];
            if (two_layer) {
                o0 = fmaxf(o0, 0.f); o1 = fmaxf(o1, 0.f);
                o2 = fmaxf(o2, 0.f); o3 = fmaxf(o3, 0.f);
            }
            if (mode & 2) {
                __half h0, l0, h1, l1;
                if (r0 < N_NODES) {
                    split1(o0, h0, l0); split1(o1, h1, l1);
                    *(uint32_t*)(out_hi + (size_t)r0 * D + cb) = packh2(h0, h1);
                    *(uint32_t*)(out_lo + (size_t)r0 * D + cb) = packh2(l0, l1);
                }
                if (r1 < N_NODES) {
                    split1(o2, h0, l0); split1(o3, h1, l1);
                    *(uint32_t*)(out_hi + (size_t)r1 * D + cb) = packh2(h0, h1);
                    *(uint32_t*)(out_lo + (size_t)r1 * D + cb) = packh2(l0, l1);
                }
            } else {
                if (r0 < N_NODES) *(float2*)(out_f32 + (size_t)r0 * D + cb) = make_float2(o0, o1);
                if (r1 < N_NODES) *(float2*)(out_f32 + (size_t)r1 * D + cb) = make_float2(o2, o3);
            }
        }
    }
}

// ===========================================================================
extern "C" void kernel_launch(void* const* d_in, const int* in_sizes, int n_in,
                              void* d_out, int out_size)
{
    const float* x  = (const float*)d_in[0];
    const void*  ei = d_in[1];
    const float* wf = (const float*)d_in[14];
    const float* bf = (const float*)d_in[15];

    static __half* ahi = nullptr;
    static __half* alo = nullptr;
    static float*  buf = nullptr;
    static bool init_done = false;
    if (!init_done) {
        cudaGetSymbolAddress((void**)&ahi, g_ahi);
        cudaGetSymbolAddress((void**)&alo, g_alo);
        cudaGetSymbolAddress((void**)&buf, g_buf);
        cudaFuncSetAttribute(mlp_tc_kernel, cudaFuncAttributeMaxDynamicSharedMemorySize, SM_TOT);
        init_done = true;
    }

    const int edge_grid = (E_EDGES + 255) / 256;
    const int node_grid = (N_NODES + 255) / 256;
    const int scan_grid = (N_NODES + 1023) / 1024;
    const int aggr_grid = (N_NODES + 15) / 16;
    const int mlp_grid  = (N_NODES + 127) / 128;

    zero_probe_kernel<<<node_grid, 256>>>((const int*)ei);
    hist_kernel<<<edge_grid, 256>>>(ei);
    scan1_kernel<<<scan_grid, 1024>>>();
    scan2_kernel<<<1, 128>>>(scan_grid);
    scan3_kernel<<<scan_grid, 1024>>>();
    fill_kernel<<<edge_grid, 256>>>(ei);

    // Block 0: aggregate(x) -> planes; MLP -> fp32 buf
    aggregate_kernel<<<aggr_grid, 256>>>(x, ahi, alo);
    mlp_tc_kernel<<<mlp_grid, 128, SM_TOT>>>(ahi, alo, buf, nullptr, nullptr,
        (const float*)d_in[2], (const float*)d_in[3],
        (const float*)d_in[4], (const float*)d_in[5], 1);

    // Block 1
    aggregate_kernel<<<aggr_grid, 256>>>(buf, ahi, alo);
    mlp_tc_kernel<<<mlp_grid, 128, SM_TOT>>>(ahi, alo, buf, nullptr, nullptr,
        (const float*)d_in[6], (const float*)d_in[7],
        (const float*)d_in[8], (const float*)d_in[9], 1);

    // Block 2: MLP writes planes (feeds final MLP directly; in-place per-row safe)
    aggregate_kernel<<<aggr_grid, 256>>>(buf, ahi, alo);
    mlp_tc_kernel<<<mlp_grid, 128, SM_TOT>>>(ahi, alo, nullptr, ahi, alo,
        (const float*)d_in[10], (const float*)d_in[11],
        (const float*)d_in[12], (const float*)d_in[13], 3);

    // Final linear: planes -> fp32 d_out
    mlp_tc_kernel<<<mlp_grid, 128, SM_TOT>>>(ahi, alo, (float*)d_out, nullptr, nullptr,
        wf, bf, nullptr, nullptr, 0);
}

// round 14
// speedup vs baseline: 1.1386x; 1.1386x over previous
#include <cuda_runtime.h>
#include <cuda_fp16.h>
#include <cstdint>

#define N_NODES 100000
#define E_EDGES 1600000
#define D 64

// Scratch (device globals: allocation-free per harness rules)
__device__ float  g_agg[(size_t)N_NODES * D];
__device__ float  g_buf[(size_t)N_NODES * D];
__device__ __half g_wh[7 * 4096];               // 7 pre-converted W^T fp16 planes
__device__ int    g_deg[N_NODES];
__device__ int    g_cur[N_NODES];
__device__ int    g_off[N_NODES];
__device__ int    g_srcs[E_EDGES];
__device__ int    g_part[128];
__device__ int    g_ei_is64;

struct WPtrs { const float* p[7]; };

// ===========================================================================
// zero + edge-index dtype probe + weight fp16 pre-conversion (one kernel)
// blocks 1..7 additionally convert W^T matrix (blockIdx-1) to g_wh.
// ===========================================================================
__global__ void zero_probe_wconv_kernel(const int* __restrict__ ei_i32, WPtrs ws) {
    __shared__ int nz;
    int t = threadIdx.x;
    int i = blockIdx.x * blockDim.x + t;
    if (i < N_NODES) { g_deg[i] = 0; g_cur[i] = 0; }
    if (blockIdx.x == 0) {
        if (t == 0) nz = 0;
        __syncthreads();
        if (t < 128 && ei_i32[2 * t + 1] != 0) atomicOr(&nz, 1);
        __syncthreads();
        if (t == 0) g_ei_is64 = (nz == 0) ? 1 : 0;
    } else if (blockIdx.x <= 7) {
        int m = blockIdx.x - 1;
        const float* w = ws.p[m];
        #pragma unroll 4
        for (int idx = t; idx < 4096; idx += 256) {
            int k = idx >> 6, n = idx & 63;      // w[k][n] -> wt[n][k]
            g_wh[m * 4096 + n * 64 + k] = __float2half_rn(__ldg(&w[idx]));
        }
    }
}

__device__ __forceinline__ int load_idx(const void* ei_raw, int pos) {
    if (g_ei_is64) return (int)__ldg(&((const long long*)ei_raw)[pos]);
    return __ldg(&((const int*)ei_raw)[pos]);
}

__global__ void hist_kernel(const void* __restrict__ ei_raw) {
    int e = blockIdx.x * blockDim.x + threadIdx.x;
    if (e >= E_EDGES) return;
    atomicAdd(&g_deg[load_idx(ei_raw, E_EDGES + e)], 1);
}

__global__ void __launch_bounds__(1024) scan1_kernel() {
    __shared__ int wsum[32];
    int i = blockIdx.x * 1024 + threadIdx.x;
    int v = (i < N_NODES) ? g_deg[i] : 0;
    int lane = threadIdx.x & 31, wid = threadIdx.x >> 5;
    int incl = v;
    #pragma unroll
    for (int d = 1; d < 32; d <<= 1) {
        int n = __shfl_up_sync(~0u, incl, d);
        if (lane >= d) incl += n;
    }
    if (lane == 31) wsum[wid] = incl;
    __syncthreads();
    if (wid == 0) {
        int s = wsum[lane];
        #pragma unroll
        for (int d = 1; d < 32; d <<= 1) {
            int n = __shfl_up_sync(~0u, s, d);
            if (lane >= d) s += n;
        }
        wsum[lane] = s;
    }
    __syncthreads();
    int woff = (wid > 0) ? wsum[wid - 1] : 0;
    if (i < N_NODES) g_off[i] = woff + incl - v;
    if (threadIdx.x == 1023) g_part[blockIdx.x] = woff + incl;
}

// Fused scan2+scan3: each block reduces g_part[0..bid) itself (<=98 values),
// then adds to its 1024 offsets. Removes the separate scan2 launch.
__global__ void __launch_bounds__(1024) scan23_kernel() {
    __shared__ int ssum[32];
    int t = threadIdx.x;
    int lane = t & 31, wid = t >> 5;
    int v = (t < blockIdx.x) ? g_part[t] : 0;     // blockIdx.x <= 97 < 1024
    #pragma unroll
    for (int d = 16; d >= 1; d >>= 1) v += __shfl_down_sync(~0u, v, d);
    if (lane == 0) ssum[wid] = v;
    __syncthreads();
    if (wid == 0) {
        int s = ssum[lane];
        #pragma unroll
        for (int d = 16; d >= 1; d >>= 1) s += __shfl_down_sync(~0u, s, d);
        if (lane == 0) ssum[0] = s;
    }
    __syncthreads();
    int add = ssum[0];
    int i = blockIdx.x * 1024 + t;
    if (i < N_NODES) g_off[i] += add;
}

__global__ void fill_kernel(const void* __restrict__ ei_raw) {
    int e = blockIdx.x * blockDim.x + threadIdx.x;
    if (e >= E_EDGES) return;
    int src = load_idx(ei_raw, e);
    int dst = load_idx(ei_raw, E_EDGES + e);
    g_srcs[g_off[dst] + atomicAdd(&g_cur[dst], 1)] = src;
}

// ===========================================================================
// agg[i] = x[i] + sum_{j in bucket(i)} x[srcs[j]]   (no atomics)
// ===========================================================================
__global__ void __launch_bounds__(256) aggregate_kernel(
    const float* __restrict__ x, float* __restrict__ agg)
{
    int node = blockIdx.x * 16 + (threadIdx.x >> 4);
    int c = threadIdx.x & 15;
    if (node >= N_NODES) return;

    int beg = __ldg(&g_off[node]);
    int cnt = __ldg(&g_deg[node]);
    float4 v = __ldg((const float4*)(x + (size_t)node * D) + c);

    int j = 0;
    for (; j + 2 <= cnt; j += 2) {
        int s0 = __ldg(&g_srcs[beg + j]);
        int s1 = __ldg(&g_srcs[beg + j + 1]);
        float4 u0 = __ldg((const float4*)(x + (size_t)s0 * D) + c);
        float4 u1 = __ldg((const float4*)(x + (size_t)s1 * D) + c);
        v.x += u0.x + u1.x; v.y += u0.y + u1.y;
        v.z += u0.z + u1.z; v.w += u0.w + u1.w;
    }
    if (j < cnt) {
        int s0 = __ldg(&g_srcs[beg + j]);
        float4 u0 = __ldg((const float4*)(x + (size_t)s0 * D) + c);
        v.x += u0.x; v.y += u0.y; v.z += u0.z; v.w += u0.w;
    }
    *((float4*)(agg + (size_t)node * D) + c) = v;
}

// ===========================================================================
// Tensor-core MLP via mma.sync.m16n8k16 FP16, 2-product split (R12 numerics).
// R14: weights arrive PRE-CONVERTED fp16 (g_wh) -> stage_w is 4 uint4
// copies/thread across ALL 128 threads (no cvt, no half-idle staging).
// CTA = 128 threads / 128 rows; warp w: rows 32w..32w+31, all 64 cols.
// ===========================================================================
#define SR 72

#define SM_BIAS1 0
#define SM_BIAS2 256
#define SM_AHI   512
#define SM_ALO   (SM_AHI + 128 * SR * 2)
#define SM_B1    (SM_ALO + 128 * SR * 2)
#define SM_B2    (SM_B1  + 64 * SR * 2)
#define SM_TOT   (SM_B2  + 64 * SR * 2)   // 55808 bytes -> 4 CTAs/SM

__device__ __forceinline__ void split1(float x, __half& h, __half& l) {
    h = __float2half_rn(x);
    l = __float2half_rn(x - __half2float(h));
}
__device__ __forceinline__ uint32_t packh2(__half a, __half b) {
    __half2 h = __halves2half2(a, b);
    return *(uint32_t*)&h;
}

// NON-volatile: pure computation, lets the compiler schedule.
__device__ __forceinline__ void mma16816(float c[4], uint32_t a0, uint32_t a1,
                                         uint32_t a2, uint32_t a3,
                                         uint32_t b0, uint32_t b1) {
    asm("mma.sync.aligned.m16n8k16.row.col.f32.f16.f16.f32 "
        "{%0,%1,%2,%3}, {%4,%5,%6,%7}, {%8,%9}, {%0,%1,%2,%3};"
        : "+f"(c[0]), "+f"(c[1]), "+f"(c[2]), "+f"(c[3])
        : "r"(a0), "r"(a1), "r"(a2), "r"(a3), "r"(b0), "r"(b1));
}

// 2-product sweep: c += Ahi@B + Alo@B  (product-type outermost)
__device__ __forceinline__ void gemm_smemA(const __half* __restrict__ Ahi,
                                           const __half* __restrict__ Alo,
                                           const __half* __restrict__ B,
                                           float c[2][8][4], int m0, int g, int tig)
{
    #pragma unroll
    for (int ks = 0; ks < 4; ks++) {
        const int k0 = ks * 16;
        uint32_t ah[2][4], al[2][4];
        #pragma unroll
        for (int mt = 0; mt < 2; mt++) {
            const __half* p0 = Ahi + (m0 + mt * 16 + g) * SR + k0 + tig * 2;
            const __half* q0 = Alo + (m0 + mt * 16 + g) * SR + k0 + tig * 2;
            ah[mt][0] = *(const uint32_t*)p0;
            ah[mt][1] = *(const uint32_t*)(p0 + 8 * SR);
            ah[mt][2] = *(const uint32_t*)(p0 + 8);
            ah[mt][3] = *(const uint32_t*)(p0 + 8 * SR + 8);
            al[mt][0] = *(const uint32_t*)q0;
            al[mt][1] = *(const uint32_t*)(q0 + 8 * SR);
            al[mt][2] = *(const uint32_t*)(q0 + 8);
            al[mt][3] = *(const uint32_t*)(q0 + 8 * SR + 8);
        }
        #pragma unroll
        for (int nt = 0; nt < 8; nt++) {
            const __half* pb = B + (nt * 8 + g) * SR + k0 + tig * 2;
            uint32_t b0 = *(const uint32_t*)pb, b1 = *(const uint32_t*)(pb + 8);
            mma16816(c[0][nt], ah[0][0], ah[0][1], ah[0][2], ah[0][3], b0, b1);
            mma16816(c[1][nt], ah[1][0], ah[1][1], ah[1][2], ah[1][3], b0, b1);
        }
        #pragma unroll
        for (int nt = 0; nt < 8; nt++) {
            const __half* pb = B + (nt * 8 + g) * SR + k0 + tig * 2;
            uint32_t b0 = *(const uint32_t*)pb, b1 = *(const uint32_t*)(pb + 8);
            mma16816(c[0][nt], al[0][0], al[0][1], al[0][2], al[0][3], b0, b1);
            mma16816(c[1][nt], al[1][0], al[1][1], al[1][2], al[1][3], b0, b1);
        }
    }
}

// stage pre-converted W^T plane: pure uint4 copy, all 128 threads
__device__ __forceinline__ void stage_wh(const __half* __restrict__ wt,
                                         __half* b, int t)
{
    #pragma unroll
    for (int j = 0; j < 4; j++) {
        int i = t + j * 128;               // 512 uint4 total
        int n = i >> 3, k8 = i & 7;
        *(uint4*)(b + n * SR + k8 * 8) = __ldg((const uint4*)wt + i);
    }
}

__global__ void __launch_bounds__(128) mlp_tc_kernel(
    const float* __restrict__ in, float* __restrict__ out,
    const __half* __restrict__ w1t, const float* __restrict__ b1,
    const __half* __restrict__ w2t, const float* __restrict__ b2,
    int two_layer)
{
    extern __shared__ char smem[];
    float* sB1f = (float*)(smem + SM_BIAS1);
    float* sB2f = (float*)(smem + SM_BIAS2);
    __half* sAhi = (__half*)(smem + SM_AHI);
    __half* sAlo = (__half*)(smem + SM_ALO);
    __half* sB1  = (__half*)(smem + SM_B1);
    __half* sB2  = (__half*)(smem + SM_B2);

    const int t = threadIdx.x;
    const int warp = t >> 5, lane = t & 31;
    const int g = lane >> 2, tig = lane & 3;
    const int m0 = warp * 32;
    const int row0 = blockIdx.x * 128;

    // ---- stage A (hi/lo fp16 split): coalesced float4 reads ----
    #pragma unroll
    for (int i = 0; i < 16; i++) {
        int idx4 = t + i * 128;
        int r = idx4 >> 4, c4 = idx4 & 15;
        int gr = row0 + r;
        float4 v = make_float4(0.f, 0.f, 0.f, 0.f);
        if (gr < N_NODES) v = __ldg((const float4*)(in + (size_t)gr * D) + c4);
        __half h0, l0, h1, l1, h2, l2, h3, l3;
        split1(v.x, h0, l0); split1(v.y, h1, l1);
        split1(v.z, h2, l2); split1(v.w, h3, l3);
        uint32_t* ph = (uint32_t*)(sAhi + r * SR + c4 * 4);
        uint32_t* pl = (uint32_t*)(sAlo + r * SR + c4 * 4);
        ph[0] = packh2(h0, h1); ph[1] = packh2(h2, h3);
        pl[0] = packh2(l0, l1); pl[1] = packh2(l2, l3);
    }
    // ---- stage W planes (pure copies) + biases ----
    stage_wh(w1t, sB1, t);
    if (two_layer) stage_wh(w2t, sB2, t);
    if (t < 16) ((float4*)sB1f)[t] = __ldg((const float4*)b1 + t);
    else if (t < 32 && two_layer) ((float4*)sB2f)[t - 16] = __ldg((const float4*)b2 + (t - 16));
    __syncthreads();   // the ONLY barrier

    float c[2][8][4];
    #pragma unroll
    for (int mt = 0; mt < 2; mt++)
        #pragma unroll
        for (int nt = 0; nt < 8; nt++)
            #pragma unroll
            for (int j = 0; j < 4; j++) c[mt][nt][j] = 0.f;

    gemm_smemA(sAhi, sAlo, sB1, c, m0, g, tig);

    if (two_layer) {
        // ---- h1 = relu(c + b1): fp16 split/pack IN REGISTERS ----
        uint32_t phi[2][8][2], plo[2][8][2];
        #pragma unroll
        for (int mt = 0; mt < 2; mt++) {
            #pragma unroll
            for (int nt = 0; nt < 8; nt++) {
                int cb = nt * 8 + tig * 2;
                float o0 = fmaxf(c[mt][nt][0] + sB1f[cb],     0.f);
                float o1 = fmaxf(c[mt][nt][1] + sB1f[cb + 1], 0.f);
                float o2 = fmaxf(c[mt][nt][2] + sB1f[cb],     0.f);
                float o3 = fmaxf(c[mt][nt][3] + sB1f[cb + 1], 0.f);
                __half h0, l0, h1, l1, h2, l2, h3, l3;
                split1(o0, h0, l0); split1(o1, h1, l1);
                split1(o2, h2, l2); split1(o3, h3, l3);
                phi[mt][nt][0] = packh2(h0, h1);
                phi[mt][nt][1] = packh2(h2, h3);
                plo[mt][nt][0] = packh2(l0, l1);
                plo[mt][nt][1] = packh2(l2, l3);
            }
        }
        #pragma unroll
        for (int mt = 0; mt < 2; mt++)
            #pragma unroll
            for (int nt = 0; nt < 8; nt++)
                #pragma unroll
                for (int j = 0; j < 4; j++) c[mt][nt][j] = 0.f;

        // ---- layer-2 GEMM: A from registers, 2 products ----
        #pragma unroll
        for (int ks = 0; ks < 4; ks++) {
            const int k0 = ks * 16;
            #pragma unroll
            for (int nt = 0; nt < 8; nt++) {
                const __half* pb = sB2 + (nt * 8 + g) * SR + k0 + tig * 2;
                uint32_t b0 = *(const uint32_t*)pb, b1 = *(const uint32_t*)(pb + 8);
                mma16816(c[0][nt], phi[0][2*ks][0], phi[0][2*ks][1],
                         phi[0][2*ks+1][0], phi[0][2*ks+1][1], b0, b1);
                mma16816(c[1][nt], phi[1][2*ks][0], phi[1][2*ks][1],
                         phi[1][2*ks+1][0], phi[1][2*ks+1][1], b0, b1);
            }
            #pragma unroll
            for (int nt = 0; nt < 8; nt++) {
                const __half* pb = sB2 + (nt * 8 + g) * SR + k0 + tig * 2;
                uint32_t b0 = *(const uint32_t*)pb, b1 = *(const uint32_t*)(pb + 8);
                mma16816(c[0][nt], plo[0][2*ks][0], plo[0][2*ks][1],
                         plo[0][2*ks+1][0], plo[0][2*ks+1][1], b0, b1);
                mma16816(c[1][nt], plo[1][2*ks][0], plo[1][2*ks][1],
                         plo[1][2*ks+1][0], plo[1][2*ks+1][1], b0, b1);
            }
        }
    }

    // ---- epilogue: bias (+ relu for GIN block), store ----
    const float* bias = two_layer ? sB2f : sB1f;
    #pragma unroll
    for (int mt = 0; mt < 2; mt++) {
        int r0 = row0 + m0 + mt * 16 + g;
        int r1 = r0 + 8;
        #pragma unroll
        for (int nt = 0; nt < 8; nt++) {
            int cb = nt * 8 + tig * 2;
            float o0 = c[mt][nt][0] + bias[cb];
            float o1 = c[mt][nt][1] + bias[cb + 1];
            float o2 = c[mt][nt][2] + bias[cb];
            float o3 = c[mt][nt][3] + bias[cb + 1];
            if (two_layer) {
                o0 = fmaxf(o0, 0.f); o1 = fmaxf(o1, 0.f);
                o2 = fmaxf(o2, 0.f); o3 = fmaxf(o3, 0.f);
            }
            if (r0 < N_NODES) *(float2*)(out + (size_t)r0 * D + cb) = make_float2(o0, o1);
            if (r1 < N_NODES) *(float2*)(out + (size_t)r1 * D + cb) = make_float2(o2, o3);
        }
    }
}

// ===========================================================================
extern "C" void kernel_launch(void* const* d_in, const int* in_sizes, int n_in,
                              void* d_out, int out_size)
{
    const float* x  = (const float*)d_in[0];
    const void*  ei = d_in[1];

    static float*  agg = nullptr;
    static float*  buf = nullptr;
    static __half* wh  = nullptr;
    static bool init_done = false;
    if (!init_done) {
        cudaGetSymbolAddress((void**)&agg, g_agg);
        cudaGetSymbolAddress((void**)&buf, g_buf);
        cudaGetSymbolAddress((void**)&wh, g_wh);
        cudaFuncSetAttribute(mlp_tc_kernel, cudaFuncAttributeMaxDynamicSharedMemorySize, SM_TOT);
        init_done = true;
    }

    const int edge_grid = (E_EDGES + 255) / 256;
    const int node_grid = (N_NODES + 255) / 256;
    const int scan_grid = (N_NODES + 1023) / 1024;
    const int aggr_grid = (N_NODES + 15) / 16;
    const int mlp_grid  = (N_NODES + 127) / 128;

    // weight order in g_wh: w1_0, w2_0, w1_1, w2_1, w1_2, w2_2, wf
    WPtrs ws;
    ws.p[0] = (const float*)d_in[2];  ws.p[1] = (const float*)d_in[4];
    ws.p[2] = (const float*)d_in[6];  ws.p[3] = (const float*)d_in[8];
    ws.p[4] = (const float*)d_in[10]; ws.p[5] = (const float*)d_in[12];
    ws.p[6] = (const float*)d_in[14];

    zero_probe_wconv_kernel<<<node_grid, 256>>>((const int*)ei, ws);
    hist_kernel<<<edge_grid, 256>>>(ei);
    scan1_kernel<<<scan_grid, 1024>>>();
    scan23_kernel<<<scan_grid, 1024>>>();
    fill_kernel<<<edge_grid, 256>>>(ei);

    // Block 0
    aggregate_kernel<<<aggr_grid, 256>>>(x, agg);
    mlp_tc_kernel<<<mlp_grid, 128, SM_TOT>>>(agg, buf,
        wh + 0 * 4096, (const float*)d_in[3],
        wh + 1 * 4096, (const float*)d_in[5], 1);

    // Block 1
    aggregate_kernel<<<aggr_grid, 256>>>(buf, agg);
    mlp_tc_kernel<<<mlp_grid, 128, SM_TOT>>>(agg, buf,
        wh + 2 * 4096, (const float*)d_in[7],
        wh + 3 * 4096, (const float*)d_in[9], 1);

    // Block 2
    aggregate_kernel<<<aggr_grid, 256>>>(buf, agg);
    mlp_tc_kernel<<<mlp_grid, 128, SM_TOT>>>(agg, buf,
        wh + 4 * 4096, (const float*)d_in[11],
        wh + 5 * 4096, (const float*)d_in[13], 1);

    // Final linear
    mlp_tc_kernel<<<mlp_grid, 128, SM_TOT>>>(buf, (float*)d_out,
        wh + 6 * 4096, (const float*)d_in[15],
        nullptr, nullptr, 0);
}